// round 2
// baseline (speedup 1.0000x reference)
#include <cuda_runtime.h>
#include <math.h>

#define Bn 8
#define Ln 1024
#define Dn 1024
#define Hn 16
#define DH 64
#define Mn 8192   // B*L rows

// ---- scratch (no cudaMalloc allowed) ----
__device__ float g_qp[(size_t)Mn * Dn];
__device__ float g_kp[(size_t)Mn * Dn];
__device__ float g_vp[(size_t)Mn * Dn];
__device__ float g_ctx[(size_t)Mn * Dn];
__device__ float g_y[(size_t)Mn * Dn];

// ============================================================
// C[m][n] = sum_k A[m][k] * W[n][k] + bias[n] (+ resid[m][n])
// 64x64 tile, BK=16, 256 threads, 4x4 per thread.
// ============================================================
__global__ __launch_bounds__(256) void gemm_nt(
    const float* __restrict__ A, const float* __restrict__ W,
    const float* __restrict__ bias, const float* __restrict__ resid,
    float* __restrict__ C, int M, int N, int K)
{
    __shared__ float As[16][68];
    __shared__ float Bs[16][68];
    int tid = threadIdx.x;
    int tx = tid & 15, ty = tid >> 4;
    int m0 = blockIdx.y << 6, n0 = blockIdx.x << 6;
    int lrow = tid >> 2;            // 0..63
    int lk4  = (tid & 3) << 2;      // 0,4,8,12

    const float* Aptr = A + (size_t)(m0 + lrow) * K + lk4;
    const float* Wptr = W + (size_t)(n0 + lrow) * K + lk4;

    float acc[4][4] = {};

    for (int k0 = 0; k0 < K; k0 += 16) {
        float4 a = *(const float4*)(Aptr + k0);
        float4 b = *(const float4*)(Wptr + k0);
        As[lk4 + 0][lrow] = a.x; As[lk4 + 1][lrow] = a.y;
        As[lk4 + 2][lrow] = a.z; As[lk4 + 3][lrow] = a.w;
        Bs[lk4 + 0][lrow] = b.x; Bs[lk4 + 1][lrow] = b.y;
        Bs[lk4 + 2][lrow] = b.z; Bs[lk4 + 3][lrow] = b.w;
        __syncthreads();
        #pragma unroll
        for (int kk = 0; kk < 16; kk++) {
            float4 af = *(const float4*)&As[kk][ty * 4];
            float4 bf = *(const float4*)&Bs[kk][tx * 4];
            float afv[4] = {af.x, af.y, af.z, af.w};
            float bfv[4] = {bf.x, bf.y, bf.z, bf.w};
            #pragma unroll
            for (int i = 0; i < 4; i++)
                #pragma unroll
                for (int j = 0; j < 4; j++)
                    acc[i][j] += afv[i] * bfv[j];
        }
        __syncthreads();
    }

    float4 bv = *(const float4*)&bias[n0 + tx * 4];
    #pragma unroll
    for (int i = 0; i < 4; i++) {
        int m = m0 + ty * 4 + i;
        size_t off = (size_t)m * N + n0 + tx * 4;
        float4 o;
        o.x = acc[i][0] + bv.x;
        o.y = acc[i][1] + bv.y;
        o.z = acc[i][2] + bv.z;
        o.w = acc[i][3] + bv.w;
        if (resid) {
            float4 rv = *(const float4*)&resid[off];
            o.x += rv.x; o.y += rv.y; o.z += rv.z; o.w += rv.w;
        }
        *(float4*)&C[off] = o;
    }
}

// ============================================================
// Attention in "view space": flat buffers interpreted as
// [128 g][1024 l2][64 d]. mask row for batch g = g % Bn.
// Unstable softmax exactly as reference: e = exp(s/8) or 0,
// denom clipped at 2e-15.
// Block: g = blockIdx.y, 32 q-rows; 8 warps x 4 rows; lane owns
// 2 output cols. K streamed in 32-row tiles.
// ============================================================
__global__ __launch_bounds__(256) void attn_kernel(
    const float* __restrict__ qp, const float* __restrict__ kp,
    const float* __restrict__ vp, const float* __restrict__ qm,
    const float* __restrict__ km, float* __restrict__ ctx)
{
    __shared__ float q_s[32][68];
    __shared__ float k_s[32][68];
    __shared__ float v_s[32][64];

    int g = blockIdx.y;
    int q0 = blockIdx.x << 5;
    int tid = threadIdx.x;
    int warp = tid >> 5, lane = tid & 31;
    int mb = g & 7;   // g % Bn

    const float* qbase = qp + (size_t)g * (Ln * DH);
    const float* kbase = kp + (size_t)g * (Ln * DH);
    const float* vbase = vp + (size_t)g * (Ln * DH);

    // load q tile [32][64]
    for (int it = tid; it < 32 * 16; it += 256) {
        int r = it >> 4, c4 = (it & 15) << 2;
        float4 v = *(const float4*)&qbase[(q0 + r) * DH + c4];
        *(float4*)&q_s[r][c4] = v;
    }

    float qmv[4];
    #pragma unroll
    for (int r = 0; r < 4; r++)
        qmv[r] = qm[mb * Ln + q0 + warp * 4 + r];

    float den[4] = {0.f, 0.f, 0.f, 0.f};
    float2 acc[4] = {{0.f, 0.f}, {0.f, 0.f}, {0.f, 0.f}, {0.f, 0.f}};

    for (int k0 = 0; k0 < Ln; k0 += 32) {
        __syncthreads();   // prev compute done / q_s visible
        for (int it = tid; it < 32 * 16; it += 256) {
            int r = it >> 4, c4 = (it & 15) << 2;
            *(float4*)&k_s[r][c4] = *(const float4*)&kbase[(k0 + r) * DH + c4];
        }
        for (int it = tid; it < 32 * 16; it += 256) {
            int r = it >> 4, c4 = (it & 15) << 2;
            *(float4*)&v_s[r][c4] = *(const float4*)&vbase[(k0 + r) * DH + c4];
        }
        __syncthreads();

        float kmv = km[mb * Ln + k0 + lane];

        // scores: lane handles k-row = lane, 4 q-rows
        float s[4] = {0.f, 0.f, 0.f, 0.f};
        const float4* k4row = (const float4*)&k_s[lane][0];
        #pragma unroll
        for (int i = 0; i < 16; i++) {
            float4 kk = k4row[i];
            #pragma unroll
            for (int r = 0; r < 4; r++) {
                float4 qq = *(const float4*)&q_s[warp * 4 + r][i * 4];
                s[r] += qq.x * kk.x + qq.y * kk.y + qq.z * kk.z + qq.w * kk.w;
            }
        }
        float e[4];
        #pragma unroll
        for (int r = 0; r < 4; r++) {
            float val = (qmv[r] * kmv == 0.f) ? 0.f : expf(s[r] * 0.125f);
            e[r] = val;
            den[r] += val;
        }
        // accumulate context: broadcast e over lanes
        #pragma unroll
        for (int kk = 0; kk < 32; kk++) {
            float2 vv = *(const float2*)&v_s[kk][lane * 2];
            #pragma unroll
            for (int r = 0; r < 4; r++) {
                float eb = __shfl_sync(0xffffffffu, e[r], kk);
                acc[r].x += eb * vv.x;
                acc[r].y += eb * vv.y;
            }
        }
    }

    // reduce denominators across lanes and write
    #pragma unroll
    for (int r = 0; r < 4; r++) {
        float d = den[r];
        #pragma unroll
        for (int o = 16; o; o >>= 1) d += __shfl_xor_sync(0xffffffffu, d, o);
        d = fmaxf(d, 2e-15f);
        int row = q0 + warp * 4 + r;
        float2 o2;
        o2.x = acc[r].x / d;
        o2.y = acc[r].y / d;
        *(float2*)&ctx[(size_t)g * (Ln * DH) + row * DH + lane * 2] = o2;
    }
}

// ============================================================
// LayerNorm per row of 1024, 256 threads x float4.
// ============================================================
__global__ __launch_bounds__(256) void ln_kernel(
    const float* __restrict__ y, const float* __restrict__ gamma,
    const float* __restrict__ beta, float* __restrict__ out)
{
    __shared__ float red[8];
    int row = blockIdx.x, tid = threadIdx.x;
    float4 v = ((const float4*)(y + (size_t)row * Dn))[tid];

    float s = v.x + v.y + v.z + v.w;
    #pragma unroll
    for (int o = 16; o; o >>= 1) s += __shfl_xor_sync(0xffffffffu, s, o);
    if ((tid & 31) == 0) red[tid >> 5] = s;
    __syncthreads();
    if (tid < 32) {
        float t = (tid < 8) ? red[tid] : 0.f;
        #pragma unroll
        for (int o = 4; o; o >>= 1) t += __shfl_xor_sync(0xffffffffu, t, o);
        if (tid == 0) red[0] = t;
    }
    __syncthreads();
    float mean = red[0] * (1.f / Dn);
    __syncthreads();

    float dx = v.x - mean, dy = v.y - mean, dz = v.z - mean, dw = v.w - mean;
    float sq = dx * dx + dy * dy + dz * dz + dw * dw;
    #pragma unroll
    for (int o = 16; o; o >>= 1) sq += __shfl_xor_sync(0xffffffffu, sq, o);
    if ((tid & 31) == 0) red[tid >> 5] = sq;
    __syncthreads();
    if (tid < 32) {
        float t = (tid < 8) ? red[tid] : 0.f;
        #pragma unroll
        for (int o = 4; o; o >>= 1) t += __shfl_xor_sync(0xffffffffu, t, o);
        if (tid == 0) red[0] = t;
    }
    __syncthreads();
    float rstd = rsqrtf(red[0] * (1.f / Dn) + 1e-5f);

    float4 g4 = ((const float4*)gamma)[tid];
    float4 b4 = ((const float4*)beta)[tid];
    float4 o4;
    o4.x = dx * rstd * g4.x + b4.x;
    o4.y = dy * rstd * g4.y + b4.y;
    o4.z = dz * rstd * g4.z + b4.z;
    o4.w = dw * rstd * g4.w + b4.w;
    ((float4*)(out + (size_t)row * Dn))[tid] = o4;
}

// ============================================================
extern "C" void kernel_launch(void* const* d_in, const int* in_sizes, int n_in,
                              void* d_out, int out_size)
{
    const float* query  = (const float*)d_in[0];
    const float* key_   = (const float*)d_in[1];
    const float* value  = (const float*)d_in[2];
    const float* q_mask = (const float*)d_in[3];
    const float* k_mask = (const float*)d_in[4];
    const float* Wq = (const float*)d_in[5];
    const float* bq = (const float*)d_in[6];
    const float* Wk = (const float*)d_in[7];
    const float* bk = (const float*)d_in[8];
    const float* Wv = (const float*)d_in[9];
    const float* bv = (const float*)d_in[10];
    const float* Wo = (const float*)d_in[11];
    const float* bo = (const float*)d_in[12];
    const float* gamma = (const float*)d_in[13];
    const float* beta  = (const float*)d_in[14];

    float *qp, *kp, *vp, *ctx, *y;
    cudaGetSymbolAddress((void**)&qp,  g_qp);
    cudaGetSymbolAddress((void**)&kp,  g_kp);
    cudaGetSymbolAddress((void**)&vp,  g_vp);
    cudaGetSymbolAddress((void**)&ctx, g_ctx);
    cudaGetSymbolAddress((void**)&y,   g_y);

    dim3 gg(Dn / 64, Mn / 64);
    gemm_nt<<<gg, 256>>>(query, Wq, bq, nullptr, qp, Mn, Dn, Dn);
    gemm_nt<<<gg, 256>>>(key_,  Wk, bk, nullptr, kp, Mn, Dn, Dn);
    gemm_nt<<<gg, 256>>>(value, Wv, bv, nullptr, vp, Mn, Dn, Dn);

    attn_kernel<<<dim3(Ln / 32, Bn * Hn), 256>>>(qp, kp, vp, q_mask, k_mask, ctx);

    gemm_nt<<<gg, 256>>>(ctx, Wo, bo, query, y, Mn, Dn, Dn);

    ln_kernel<<<Mn, 256>>>(y, gamma, beta, (float*)d_out);
}

// round 9
// speedup vs baseline: 1.4857x; 1.4857x over previous
#include <cuda_runtime.h>
#include <cuda_bf16.h>
#include <math.h>
#include <stdint.h>

#define Bn 8
#define Ln 1024
#define Dn 1024
#define Hn 16
#define DH 64
#define Mn 8192   // B*L rows

// ---- fp32 scratch ----
__device__ float g_qp[(size_t)Mn * Dn];
__device__ float g_kp[(size_t)Mn * Dn];
__device__ float g_vp[(size_t)Mn * Dn];
__device__ float g_ctx[(size_t)Mn * Dn];
__device__ float g_y[(size_t)Mn * Dn];

// ---- bf16 hi/lo planes ----
__device__ __align__(128) __nv_bfloat16 g_qh[(size_t)Mn * Dn];
__device__ __align__(128) __nv_bfloat16 g_ql[(size_t)Mn * Dn];
__device__ __align__(128) __nv_bfloat16 g_kh[(size_t)Mn * Dn];
__device__ __align__(128) __nv_bfloat16 g_kl[(size_t)Mn * Dn];
__device__ __align__(128) __nv_bfloat16 g_vh[(size_t)Mn * Dn];
__device__ __align__(128) __nv_bfloat16 g_vl[(size_t)Mn * Dn];
__device__ __align__(128) __nv_bfloat16 g_ch[(size_t)Mn * Dn];
__device__ __align__(128) __nv_bfloat16 g_cl[(size_t)Mn * Dn];
__device__ __align__(128) __nv_bfloat16 g_wqh[(size_t)Dn * Dn];
__device__ __align__(128) __nv_bfloat16 g_wql[(size_t)Dn * Dn];
__device__ __align__(128) __nv_bfloat16 g_wkh[(size_t)Dn * Dn];
__device__ __align__(128) __nv_bfloat16 g_wkl[(size_t)Dn * Dn];
__device__ __align__(128) __nv_bfloat16 g_wvh[(size_t)Dn * Dn];
__device__ __align__(128) __nv_bfloat16 g_wvl[(size_t)Dn * Dn];
__device__ __align__(128) __nv_bfloat16 g_woh[(size_t)Dn * Dn];
__device__ __align__(128) __nv_bfloat16 g_wol[(size_t)Dn * Dn];

// ============================================================
// helpers
// ============================================================
__device__ __forceinline__ uint32_t smem_u32(const void* p) {
    uint32_t a;
    asm("{ .reg .u64 t; cvta.to.shared.u64 t, %1; cvt.u32.u64 %0, t; }"
        : "=r"(a) : "l"(p));
    return a;
}

__device__ __forceinline__ void ldm_x4(uint32_t* r, uint32_t addr) {
    asm volatile("ldmatrix.sync.aligned.m8n8.x4.shared.b16 {%0,%1,%2,%3}, [%4];"
                 : "=r"(r[0]), "=r"(r[1]), "=r"(r[2]), "=r"(r[3]) : "r"(addr));
}
__device__ __forceinline__ void ldm_x2(uint32_t* r, uint32_t addr) {
    asm volatile("ldmatrix.sync.aligned.m8n8.x2.shared.b16 {%0,%1}, [%2];"
                 : "=r"(r[0]), "=r"(r[1]) : "r"(addr));
}
__device__ __forceinline__ void mma16816(float* d, const uint32_t* a, const uint32_t* b) {
    asm volatile(
        "mma.sync.aligned.m16n8k16.row.col.f32.bf16.bf16.f32 "
        "{%0,%1,%2,%3}, {%4,%5,%6,%7}, {%8,%9}, {%0,%1,%2,%3};"
        : "+f"(d[0]), "+f"(d[1]), "+f"(d[2]), "+f"(d[3])
        : "r"(a[0]), "r"(a[1]), "r"(a[2]), "r"(a[3]), "r"(b[0]), "r"(b[1]));
}
#define CP16(sa, gp) \
    asm volatile("cp.async.cg.shared.global [%0], [%1], 16;" :: "r"(sa), "l"(gp))
#define CP_COMMIT() asm volatile("cp.async.commit_group;" ::: "memory")
#define CP_WAIT1()  asm volatile("cp.async.wait_group 1;" ::: "memory")
#define CP_WAIT0()  asm volatile("cp.async.wait_group 0;" ::: "memory")

// ============================================================
// split fp32 -> (hi, lo) bf16 planes
// ============================================================
__global__ __launch_bounds__(256) void split_kernel(
    const float* __restrict__ in, __nv_bfloat16* __restrict__ hi,
    __nv_bfloat16* __restrict__ lo, int n4)
{
    int i = blockIdx.x * 256 + threadIdx.x;
    if (i >= n4) return;
    float4 v = ((const float4*)in)[i];
    __nv_bfloat16 h0 = __float2bfloat16_rn(v.x);
    __nv_bfloat16 h1 = __float2bfloat16_rn(v.y);
    __nv_bfloat16 h2 = __float2bfloat16_rn(v.z);
    __nv_bfloat16 h3 = __float2bfloat16_rn(v.w);
    __nv_bfloat16 l0 = __float2bfloat16_rn(v.x - __bfloat162float(h0));
    __nv_bfloat16 l1 = __float2bfloat16_rn(v.y - __bfloat162float(h1));
    __nv_bfloat16 l2 = __float2bfloat16_rn(v.z - __bfloat162float(h2));
    __nv_bfloat16 l3 = __float2bfloat16_rn(v.w - __bfloat162float(h3));
    uint2 hp, lp;
    hp.x = (uint32_t)__bfloat16_as_ushort(h0) | ((uint32_t)__bfloat16_as_ushort(h1) << 16);
    hp.y = (uint32_t)__bfloat16_as_ushort(h2) | ((uint32_t)__bfloat16_as_ushort(h3) << 16);
    lp.x = (uint32_t)__bfloat16_as_ushort(l0) | ((uint32_t)__bfloat16_as_ushort(l1) << 16);
    lp.y = (uint32_t)__bfloat16_as_ushort(l2) | ((uint32_t)__bfloat16_as_ushort(l3) << 16);
    ((uint2*)hi)[i] = hp;
    ((uint2*)lo)[i] = lp;
}

// ============================================================
// HMMA GEMM: C[m][n] = sum_k A[m][k]*W[n][k] + bias[n] (+resid)
// CTA 128x128, BK=32, 8 warps (2m x 4n of 64x32), bf16 3-term.
// smem: 2 stages x 4 planes x [128 rows x 80B]
// ============================================================
#define RS     80u
#define PLANE  10240u
#define STAGE  40960u
#define GM_SMEM (2 * 40960)

__global__ __launch_bounds__(256) void gemm_mma(
    const __nv_bfloat16* __restrict__ Ah, const __nv_bfloat16* __restrict__ Al,
    const __nv_bfloat16* __restrict__ Bh, const __nv_bfloat16* __restrict__ Bl,
    const float* __restrict__ bias, const float* __restrict__ resid,
    float* __restrict__ C)
{
    extern __shared__ __align__(128) char sm_raw[];
    const uint32_t base = smem_u32(sm_raw);
    const int tid = threadIdx.x;
    const int lane = tid & 31;
    const int wid = tid >> 5;
    const int m0 = blockIdx.y << 7;
    const int n0 = blockIdx.x << 7;

    // cp.async source/dest mapping: thread -> (row, 16-col segment)
    const int prow = tid >> 1;
    const int pseg = tid & 1;
    const size_t gA = (size_t)(m0 + prow) * Dn + pseg * 16;
    const size_t gB = (size_t)(n0 + prow) * Dn + pseg * 16;
    const uint32_t so = (uint32_t)prow * RS + (uint32_t)pseg * 32;

    // ldmatrix fragment base offsets
    const uint32_t a_off = ((uint32_t)((wid & 1) * 64 + (lane & 15))) * RS
                         + (uint32_t)(lane >> 4) * 16;
    const uint32_t b_off = ((uint32_t)((wid >> 1) * 32 + (lane & 7))) * RS
                         + (uint32_t)((lane >> 3) & 1) * 16 + 2 * PLANE;

    float acc[4][4][4] = {};

    // prologue: stage 0 <- k-step 0
    {
        uint32_t sb = base + so;
        size_t ka = gA, kb = gB;
        CP16(sb,                 Ah + ka);  CP16(sb + 16,             Ah + ka + 8);
        CP16(sb + PLANE,         Al + ka);  CP16(sb + PLANE + 16,     Al + ka + 8);
        CP16(sb + 2 * PLANE,     Bh + kb);  CP16(sb + 2 * PLANE + 16, Bh + kb + 8);
        CP16(sb + 3 * PLANE,     Bl + kb);  CP16(sb + 3 * PLANE + 16, Bl + kb + 8);
        CP_COMMIT();
    }

    for (int t = 0; t < 32; t++) {
        if (t + 1 < 32) {
            uint32_t sb = base + ((t + 1) & 1) * STAGE + so;
            size_t ka = gA + (size_t)(t + 1) * 32;
            size_t kb = gB + (size_t)(t + 1) * 32;
            CP16(sb,                 Ah + ka);  CP16(sb + 16,             Ah + ka + 8);
            CP16(sb + PLANE,         Al + ka);  CP16(sb + PLANE + 16,     Al + ka + 8);
            CP16(sb + 2 * PLANE,     Bh + kb);  CP16(sb + 2 * PLANE + 16, Bh + kb + 8);
            CP16(sb + 3 * PLANE,     Bl + kb);  CP16(sb + 3 * PLANE + 16, Bl + kb + 8);
            CP_COMMIT();
            CP_WAIT1();
        } else {
            CP_WAIT0();
        }
        __syncthreads();

        const uint32_t sb = base + (t & 1) * STAGE;
        #pragma unroll
        for (int kk = 0; kk < 32; kk += 16) {
            uint32_t ah[4][4], al[4][4], bh[4][2], bl[4][2];
            #pragma unroll
            for (int i = 0; i < 4; i++)
                ldm_x4(ah[i], sb + a_off + (uint32_t)i * (16 * RS) + kk * 2);
            #pragma unroll
            for (int i = 0; i < 4; i++)
                ldm_x4(al[i], sb + PLANE + a_off + (uint32_t)i * (16 * RS) + kk * 2);
            #pragma unroll
            for (int j = 0; j < 4; j++)
                ldm_x2(bh[j], sb + b_off + (uint32_t)j * (8 * RS) + kk * 2);
            #pragma unroll
            for (int j = 0; j < 4; j++)
                ldm_x2(bl[j], sb + PLANE + b_off + (uint32_t)j * (8 * RS) + kk * 2);

            #pragma unroll
            for (int i = 0; i < 4; i++)
                #pragma unroll
                for (int j = 0; j < 4; j++) {
                    mma16816(acc[i][j], ah[i], bh[j]);
                    mma16816(acc[i][j], ah[i], bl[j]);
                    mma16816(acc[i][j], al[i], bh[j]);
                }
        }
        __syncthreads();
    }

    // epilogue
    const int rbase = m0 + (wid & 1) * 64 + (lane >> 2);
    const int cbase = n0 + (wid >> 1) * 32 + (lane & 3) * 2;
    #pragma unroll
    for (int i = 0; i < 4; i++) {
        #pragma unroll
        for (int j = 0; j < 4; j++) {
            int rrow = rbase + i * 16;
            int col  = cbase + j * 8;
            float b0 = bias[col], b1 = bias[col + 1];
            float2 o0, o1;
            o0.x = acc[i][j][0] + b0;  o0.y = acc[i][j][1] + b1;
            o1.x = acc[i][j][2] + b0;  o1.y = acc[i][j][3] + b1;
            size_t off0 = (size_t)rrow * Dn + col;
            size_t off1 = (size_t)(rrow + 8) * Dn + col;
            if (resid) {
                float2 r0 = *(const float2*)&resid[off0];
                float2 r1 = *(const float2*)&resid[off1];
                o0.x += r0.x; o0.y += r0.y;
                o1.x += r1.x; o1.y += r1.y;
            }
            *(float2*)&C[off0] = o0;
            *(float2*)&C[off1] = o1;
        }
    }
}

// ============================================================
// Attention (view-space flash-style, fp32 SIMT) — unchanged
// ============================================================
__global__ __launch_bounds__(256) void attn_kernel(
    const float* __restrict__ qp, const float* __restrict__ kp,
    const float* __restrict__ vp, const float* __restrict__ qm,
    const float* __restrict__ km, float* __restrict__ ctx)
{
    __shared__ float q_s[32][68];
    __shared__ float k_s[32][68];
    __shared__ float v_s[32][64];

    int g = blockIdx.y;
    int q0 = blockIdx.x << 5;
    int tid = threadIdx.x;
    int warp = tid >> 5, lane = tid & 31;
    int mb = g & 7;

    const float* qbase = qp + (size_t)g * (Ln * DH);
    const float* kbase = kp + (size_t)g * (Ln * DH);
    const float* vbase = vp + (size_t)g * (Ln * DH);

    for (int it = tid; it < 32 * 16; it += 256) {
        int rr = it >> 4, c4 = (it & 15) << 2;
        *(float4*)&q_s[rr][c4] = *(const float4*)&qbase[(q0 + rr) * DH + c4];
    }

    float qmv[4];
    #pragma unroll
    for (int rr = 0; rr < 4; rr++)
        qmv[rr] = qm[mb * Ln + q0 + warp * 4 + rr];

    float den[4] = {0.f, 0.f, 0.f, 0.f};
    float2 acc[4] = {{0.f, 0.f}, {0.f, 0.f}, {0.f, 0.f}, {0.f, 0.f}};

    for (int k0 = 0; k0 < Ln; k0 += 32) {
        __syncthreads();
        for (int it = tid; it < 32 * 16; it += 256) {
            int rr = it >> 4, c4 = (it & 15) << 2;
            *(float4*)&k_s[rr][c4] = *(const float4*)&kbase[(k0 + rr) * DH + c4];
        }
        for (int it = tid; it < 32 * 16; it += 256) {
            int rr = it >> 4, c4 = (it & 15) << 2;
            *(float4*)&v_s[rr][c4] = *(const float4*)&vbase[(k0 + rr) * DH + c4];
        }
        __syncthreads();

        float kmv = km[mb * Ln + k0 + lane];

        float s[4] = {0.f, 0.f, 0.f, 0.f};
        const float4* k4row = (const float4*)&k_s[lane][0];
        #pragma unroll
        for (int i = 0; i < 16; i++) {
            float4 kk = k4row[i];
            #pragma unroll
            for (int rr = 0; rr < 4; rr++) {
                float4 qq = *(const float4*)&q_s[warp * 4 + rr][i * 4];
                s[rr] += qq.x * kk.x + qq.y * kk.y + qq.z * kk.z + qq.w * kk.w;
            }
        }
        float e[4];
        #pragma unroll
        for (int rr = 0; rr < 4; rr++) {
            float val = (qmv[rr] * kmv == 0.f) ? 0.f : expf(s[rr] * 0.125f);
            e[rr] = val;
            den[rr] += val;
        }
        #pragma unroll
        for (int kk = 0; kk < 32; kk++) {
            float2 vv = *(const float2*)&v_s[kk][lane * 2];
            #pragma unroll
            for (int rr = 0; rr < 4; rr++) {
                float eb = __shfl_sync(0xffffffffu, e[rr], kk);
                acc[rr].x += eb * vv.x;
                acc[rr].y += eb * vv.y;
            }
        }
    }

    #pragma unroll
    for (int rr = 0; rr < 4; rr++) {
        float d = den[rr];
        #pragma unroll
        for (int o = 16; o; o >>= 1) d += __shfl_xor_sync(0xffffffffu, d, o);
        d = fmaxf(d, 2e-15f);
        int row = q0 + warp * 4 + rr;
        float2 o2;
        o2.x = acc[rr].x / d;
        o2.y = acc[rr].y / d;
        *(float2*)&ctx[(size_t)g * (Ln * DH) + row * DH + lane * 2] = o2;
    }
}

// ============================================================
// LayerNorm — unchanged
// ============================================================
__global__ __launch_bounds__(256) void ln_kernel(
    const float* __restrict__ y, const float* __restrict__ gamma,
    const float* __restrict__ beta, float* __restrict__ out)
{
    __shared__ float red[8];
    int row = blockIdx.x, tid = threadIdx.x;
    float4 v = ((const float4*)(y + (size_t)row * Dn))[tid];

    float s = v.x + v.y + v.z + v.w;
    #pragma unroll
    for (int o = 16; o; o >>= 1) s += __shfl_xor_sync(0xffffffffu, s, o);
    if ((tid & 31) == 0) red[tid >> 5] = s;
    __syncthreads();
    if (tid < 32) {
        float t = (tid < 8) ? red[tid] : 0.f;
        #pragma unroll
        for (int o = 4; o; o >>= 1) t += __shfl_xor_sync(0xffffffffu, t, o);
        if (tid == 0) red[0] = t;
    }
    __syncthreads();
    float mean = red[0] * (1.f / Dn);
    __syncthreads();

    float dx = v.x - mean, dy = v.y - mean, dz = v.z - mean, dw = v.w - mean;
    float sq = dx * dx + dy * dy + dz * dz + dw * dw;
    #pragma unroll
    for (int o = 16; o; o >>= 1) sq += __shfl_xor_sync(0xffffffffu, sq, o);
    if ((tid & 31) == 0) red[tid >> 5] = sq;
    __syncthreads();
    if (tid < 32) {
        float t = (tid < 8) ? red[tid] : 0.f;
        #pragma unroll
        for (int o = 4; o; o >>= 1) t += __shfl_xor_sync(0xffffffffu, t, o);
        if (tid == 0) red[0] = t;
    }
    __syncthreads();
    float rstd = rsqrtf(red[0] * (1.f / Dn) + 1e-5f);

    float4 g4 = ((const float4*)gamma)[tid];
    float4 b4 = ((const float4*)beta)[tid];
    float4 o4;
    o4.x = dx * rstd * g4.x + b4.x;
    o4.y = dy * rstd * g4.y + b4.y;
    o4.z = dz * rstd * g4.z + b4.z;
    o4.w = dw * rstd * g4.w + b4.w;
    ((float4*)(out + (size_t)row * Dn))[tid] = o4;
}

// ============================================================
extern "C" void kernel_launch(void* const* d_in, const int* in_sizes, int n_in,
                              void* d_out, int out_size)
{
    const float* query  = (const float*)d_in[0];
    const float* key_   = (const float*)d_in[1];
    const float* value  = (const float*)d_in[2];
    const float* q_mask = (const float*)d_in[3];
    const float* k_mask = (const float*)d_in[4];
    const float* Wq = (const float*)d_in[5];
    const float* bq = (const float*)d_in[6];
    const float* Wk = (const float*)d_in[7];
    const float* bk = (const float*)d_in[8];
    const float* Wv = (const float*)d_in[9];
    const float* bv = (const float*)d_in[10];
    const float* Wo = (const float*)d_in[11];
    const float* bo = (const float*)d_in[12];
    const float* gamma = (const float*)d_in[13];
    const float* beta  = (const float*)d_in[14];

    float *qp, *kp, *vp, *ctx, *y;
    cudaGetSymbolAddress((void**)&qp,  g_qp);
    cudaGetSymbolAddress((void**)&kp,  g_kp);
    cudaGetSymbolAddress((void**)&vp,  g_vp);
    cudaGetSymbolAddress((void**)&ctx, g_ctx);
    cudaGetSymbolAddress((void**)&y,   g_y);

    __nv_bfloat16 *qh, *ql, *kh, *kl, *vh, *vl, *ch, *cl;
    __nv_bfloat16 *wqh, *wql, *wkh, *wkl, *wvh, *wvl, *woh, *wol;
    cudaGetSymbolAddress((void**)&qh, g_qh);  cudaGetSymbolAddress((void**)&ql, g_ql);
    cudaGetSymbolAddress((void**)&kh, g_kh);  cudaGetSymbolAddress((void**)&kl, g_kl);
    cudaGetSymbolAddress((void**)&vh, g_vh);  cudaGetSymbolAddress((void**)&vl, g_vl);
    cudaGetSymbolAddress((void**)&ch, g_ch);  cudaGetSymbolAddress((void**)&cl, g_cl);
    cudaGetSymbolAddress((void**)&wqh, g_wqh); cudaGetSymbolAddress((void**)&wql, g_wql);
    cudaGetSymbolAddress((void**)&wkh, g_wkh); cudaGetSymbolAddress((void**)&wkl, g_wkl);
    cudaGetSymbolAddress((void**)&wvh, g_wvh); cudaGetSymbolAddress((void**)&wvl, g_wvl);
    cudaGetSymbolAddress((void**)&woh, g_woh); cudaGetSymbolAddress((void**)&wol, g_wol);

    static int smem_set = 0;
    if (!smem_set) {
        cudaFuncSetAttribute(gemm_mma, cudaFuncAttributeMaxDynamicSharedMemorySize, GM_SMEM);
        smem_set = 1;
    }

    const int n4_act = (Mn * Dn) / 4;   // 2097152
    const int n4_w   = (Dn * Dn) / 4;   // 262144

    split_kernel<<<n4_act / 256, 256>>>(query, qh, ql, n4_act);
    split_kernel<<<n4_act / 256, 256>>>(key_,  kh, kl, n4_act);
    split_kernel<<<n4_act / 256, 256>>>(value, vh, vl, n4_act);
    split_kernel<<<n4_w / 256, 256>>>(Wq, wqh, wql, n4_w);
    split_kernel<<<n4_w / 256, 256>>>(Wk, wkh, wkl, n4_w);
    split_kernel<<<n4_w / 256, 256>>>(Wv, wvh, wvl, n4_w);
    split_kernel<<<n4_w / 256, 256>>>(Wo, woh, wol, n4_w);

    dim3 gg(Dn / 128, Mn / 128);
    gemm_mma<<<gg, 256, GM_SMEM>>>(qh, ql, wqh, wql, bq, nullptr, qp);
    gemm_mma<<<gg, 256, GM_SMEM>>>(kh, kl, wkh, wkl, bk, nullptr, kp);
    gemm_mma<<<gg, 256, GM_SMEM>>>(vh, vl, wvh, wvl, bv, nullptr, vp);

    attn_kernel<<<dim3(Ln / 32, Bn * Hn), 256>>>(qp, kp, vp, q_mask, k_mask, ctx);

    split_kernel<<<n4_act / 256, 256>>>(ctx, ch, cl, n4_act);
    gemm_mma<<<gg, 256, GM_SMEM>>>(ch, cl, woh, wol, bo, query, y);

    ln_kernel<<<Mn, 256>>>(y, gamma, beta, (float*)d_out);
}

// round 11
// speedup vs baseline: 2.8567x; 1.9228x over previous
#include <cuda_runtime.h>
#include <cuda_bf16.h>
#include <math.h>
#include <stdint.h>

#define Bn 8
#define Ln 1024
#define Dn 1024
#define Hn 16
#define DH 64
#define Mn 8192   // B*L rows

// ---- scratch (no cudaMalloc allowed) ----
__device__ float g_y[(size_t)Mn * Dn];

// input split scratch (reused for query/key/value, stream-serial)
__device__ __align__(128) __nv_bfloat16 g_sh[(size_t)Mn * Dn];
__device__ __align__(128) __nv_bfloat16 g_sl[(size_t)Mn * Dn];
// projected Q/K/V hi/lo planes
__device__ __align__(128) __nv_bfloat16 g_qh[(size_t)Mn * Dn];
__device__ __align__(128) __nv_bfloat16 g_ql[(size_t)Mn * Dn];
__device__ __align__(128) __nv_bfloat16 g_kh[(size_t)Mn * Dn];
__device__ __align__(128) __nv_bfloat16 g_kl[(size_t)Mn * Dn];
__device__ __align__(128) __nv_bfloat16 g_vh[(size_t)Mn * Dn];
__device__ __align__(128) __nv_bfloat16 g_vl[(size_t)Mn * Dn];
// context hi/lo
__device__ __align__(128) __nv_bfloat16 g_ch[(size_t)Mn * Dn];
__device__ __align__(128) __nv_bfloat16 g_cl[(size_t)Mn * Dn];
// weight hi/lo planes
__device__ __align__(128) __nv_bfloat16 g_wqh[(size_t)Dn * Dn];
__device__ __align__(128) __nv_bfloat16 g_wql[(size_t)Dn * Dn];
__device__ __align__(128) __nv_bfloat16 g_wkh[(size_t)Dn * Dn];
__device__ __align__(128) __nv_bfloat16 g_wkl[(size_t)Dn * Dn];
__device__ __align__(128) __nv_bfloat16 g_wvh[(size_t)Dn * Dn];
__device__ __align__(128) __nv_bfloat16 g_wvl[(size_t)Dn * Dn];
__device__ __align__(128) __nv_bfloat16 g_woh[(size_t)Dn * Dn];
__device__ __align__(128) __nv_bfloat16 g_wol[(size_t)Dn * Dn];

// ============================================================
// helpers
// ============================================================
__device__ __forceinline__ uint32_t smem_u32(const void* p) {
    uint32_t a;
    asm("{ .reg .u64 t; cvta.to.shared.u64 t, %1; cvt.u32.u64 %0, t; }"
        : "=r"(a) : "l"(p));
    return a;
}
__device__ __forceinline__ void ldm_x4(uint32_t* r, uint32_t addr) {
    asm volatile("ldmatrix.sync.aligned.m8n8.x4.shared.b16 {%0,%1,%2,%3}, [%4];"
                 : "=r"(r[0]), "=r"(r[1]), "=r"(r[2]), "=r"(r[3]) : "r"(addr));
}
__device__ __forceinline__ void ldm_x2(uint32_t* r, uint32_t addr) {
    asm volatile("ldmatrix.sync.aligned.m8n8.x2.shared.b16 {%0,%1}, [%2];"
                 : "=r"(r[0]), "=r"(r[1]) : "r"(addr));
}
__device__ __forceinline__ void ldm_x2t(uint32_t* r, uint32_t addr) {
    asm volatile("ldmatrix.sync.aligned.m8n8.x2.trans.shared.b16 {%0,%1}, [%2];"
                 : "=r"(r[0]), "=r"(r[1]) : "r"(addr));
}
__device__ __forceinline__ void mma16816(float* d, const uint32_t* a, const uint32_t* b) {
    asm volatile(
        "mma.sync.aligned.m16n8k16.row.col.f32.bf16.bf16.f32 "
        "{%0,%1,%2,%3}, {%4,%5,%6,%7}, {%8,%9}, {%0,%1,%2,%3};"
        : "+f"(d[0]), "+f"(d[1]), "+f"(d[2]), "+f"(d[3])
        : "r"(a[0]), "r"(a[1]), "r"(a[2]), "r"(a[3]), "r"(b[0]), "r"(b[1]));
}
#define CP16(sa, gp) \
    asm volatile("cp.async.cg.shared.global [%0], [%1], 16;" :: "r"(sa), "l"(gp))
#define CP_COMMIT() asm volatile("cp.async.commit_group;" ::: "memory")
#define CP_WAIT1()  asm volatile("cp.async.wait_group 1;" ::: "memory")
#define CP_WAIT0()  asm volatile("cp.async.wait_group 0;" ::: "memory")

__device__ __forceinline__ uint32_t pack2(__nv_bfloat16 a, __nv_bfloat16 b) {
    return (uint32_t)__bfloat16_as_ushort(a) | ((uint32_t)__bfloat16_as_ushort(b) << 16);
}
// split 2 fp32 into packed bf16 hi + lo words
__device__ __forceinline__ void split2(float a, float b, uint32_t& hi, uint32_t& lo) {
    __nv_bfloat16 ha = __float2bfloat16_rn(a), hb = __float2bfloat16_rn(b);
    __nv_bfloat16 la = __float2bfloat16_rn(a - __bfloat162float(ha));
    __nv_bfloat16 lb = __float2bfloat16_rn(b - __bfloat162float(hb));
    hi = pack2(ha, hb);
    lo = pack2(la, lb);
}

// ============================================================
// split fp32 -> (hi, lo) bf16 planes
// ============================================================
__global__ __launch_bounds__(256) void split_kernel(
    const float* __restrict__ in, __nv_bfloat16* __restrict__ hi,
    __nv_bfloat16* __restrict__ lo, int n4)
{
    int i = blockIdx.x * 256 + threadIdx.x;
    if (i >= n4) return;
    float4 v = ((const float4*)in)[i];
    uint32_t h0, l0, h1, l1;
    split2(v.x, v.y, h0, l0);
    split2(v.z, v.w, h1, l1);
    uint2 hp = {h0, h1}, lp = {l0, l1};
    ((uint2*)hi)[i] = hp;
    ((uint2*)lo)[i] = lp;
}

// ============================================================
// HMMA GEMM: acc = sum_k A[m][k]*W[n][k] + bias[n] (+resid)
// out: fp32 Cf and/or bf16 hi/lo planes Oh/Ol
// CTA 128x128, BK=32, 8 warps (2m x 4n of 64x32), bf16 3-term.
// ============================================================
#define RS     80u
#define PLANE  10240u
#define STAGE  40960u
#define GM_SMEM (2 * 40960)

__global__ __launch_bounds__(256) void gemm_mma(
    const __nv_bfloat16* __restrict__ Ah, const __nv_bfloat16* __restrict__ Al,
    const __nv_bfloat16* __restrict__ Bh, const __nv_bfloat16* __restrict__ Bl,
    const float* __restrict__ bias, const float* __restrict__ resid,
    float* __restrict__ Cf, __nv_bfloat16* __restrict__ Oh,
    __nv_bfloat16* __restrict__ Ol)
{
    extern __shared__ __align__(128) char sm_raw[];
    const uint32_t base = smem_u32(sm_raw);
    const int tid = threadIdx.x;
    const int lane = tid & 31;
    const int wid = tid >> 5;
    const int m0 = blockIdx.y << 7;
    const int n0 = blockIdx.x << 7;

    const int prow = tid >> 1;
    const int pseg = tid & 1;
    const size_t gA = (size_t)(m0 + prow) * Dn + pseg * 16;
    const size_t gB = (size_t)(n0 + prow) * Dn + pseg * 16;
    const uint32_t so = (uint32_t)prow * RS + (uint32_t)pseg * 32;

    const uint32_t a_off = ((uint32_t)((wid & 1) * 64 + (lane & 15))) * RS
                         + (uint32_t)(lane >> 4) * 16;
    const uint32_t b_off = ((uint32_t)((wid >> 1) * 32 + (lane & 7))) * RS
                         + (uint32_t)((lane >> 3) & 1) * 16 + 2 * PLANE;

    float acc[4][4][4] = {};

    {
        uint32_t sb = base + so;
        CP16(sb,                 Ah + gA);  CP16(sb + 16,             Ah + gA + 8);
        CP16(sb + PLANE,         Al + gA);  CP16(sb + PLANE + 16,     Al + gA + 8);
        CP16(sb + 2 * PLANE,     Bh + gB);  CP16(sb + 2 * PLANE + 16, Bh + gB + 8);
        CP16(sb + 3 * PLANE,     Bl + gB);  CP16(sb + 3 * PLANE + 16, Bl + gB + 8);
        CP_COMMIT();
    }

    for (int t = 0; t < 32; t++) {
        if (t + 1 < 32) {
            uint32_t sb = base + ((t + 1) & 1) * STAGE + so;
            size_t ka = gA + (size_t)(t + 1) * 32;
            size_t kb = gB + (size_t)(t + 1) * 32;
            CP16(sb,                 Ah + ka);  CP16(sb + 16,             Ah + ka + 8);
            CP16(sb + PLANE,         Al + ka);  CP16(sb + PLANE + 16,     Al + ka + 8);
            CP16(sb + 2 * PLANE,     Bh + kb);  CP16(sb + 2 * PLANE + 16, Bh + kb + 8);
            CP16(sb + 3 * PLANE,     Bl + kb);  CP16(sb + 3 * PLANE + 16, Bl + kb + 8);
            CP_COMMIT();
            CP_WAIT1();
        } else {
            CP_WAIT0();
        }
        __syncthreads();

        const uint32_t sb = base + (t & 1) * STAGE;
        #pragma unroll
        for (int kk = 0; kk < 32; kk += 16) {
            uint32_t ah[4][4], al[4][4], bh[4][2], bl[4][2];
            #pragma unroll
            for (int i = 0; i < 4; i++)
                ldm_x4(ah[i], sb + a_off + (uint32_t)i * (16 * RS) + kk * 2);
            #pragma unroll
            for (int i = 0; i < 4; i++)
                ldm_x4(al[i], sb + PLANE + a_off + (uint32_t)i * (16 * RS) + kk * 2);
            #pragma unroll
            for (int j = 0; j < 4; j++)
                ldm_x2(bh[j], sb + b_off + (uint32_t)j * (8 * RS) + kk * 2);
            #pragma unroll
            for (int j = 0; j < 4; j++)
                ldm_x2(bl[j], sb + PLANE + b_off + (uint32_t)j * (8 * RS) + kk * 2);

            #pragma unroll
            for (int i = 0; i < 4; i++)
                #pragma unroll
                for (int j = 0; j < 4; j++) {
                    mma16816(acc[i][j], ah[i], bh[j]);
                    mma16816(acc[i][j], ah[i], bl[j]);
                    mma16816(acc[i][j], al[i], bh[j]);
                }
        }
        __syncthreads();
    }

    // epilogue
    const int rbase = m0 + (wid & 1) * 64 + (lane >> 2);
    const int cbase = n0 + (wid >> 1) * 32 + (lane & 3) * 2;
    #pragma unroll
    for (int i = 0; i < 4; i++) {
        #pragma unroll
        for (int j = 0; j < 4; j++) {
            int rrow = rbase + i * 16;
            int col  = cbase + j * 8;
            float b0 = bias[col], b1 = bias[col + 1];
            float o0 = acc[i][j][0] + b0, o1 = acc[i][j][1] + b1;
            float o2 = acc[i][j][2] + b0, o3 = acc[i][j][3] + b1;
            size_t off0 = (size_t)rrow * Dn + col;
            size_t off1 = (size_t)(rrow + 8) * Dn + col;
            if (resid) {
                float2 r0 = *(const float2*)&resid[off0];
                float2 r1 = *(const float2*)&resid[off1];
                o0 += r0.x; o1 += r0.y; o2 += r1.x; o3 += r1.y;
            }
            if (Cf) {
                float2 w0 = {o0, o1}, w1 = {o2, o3};
                *(float2*)&Cf[off0] = w0;
                *(float2*)&Cf[off1] = w1;
            }
            if (Oh) {
                uint32_t h0, l0, h1, l1;
                split2(o0, o1, h0, l0);
                split2(o2, o3, h1, l1);
                ((uint32_t*)Oh)[off0 >> 1] = h0;
                ((uint32_t*)Ol)[off0 >> 1] = l0;
                ((uint32_t*)Oh)[off1 >> 1] = h1;
                ((uint32_t*)Ol)[off1 >> 1] = l1;
            }
        }
    }
}

// ============================================================
// Tensor-core attention, view-space [128 g][1024][64].
// CTA: 64 q-rows (4 warps x 16), streams 64-key tiles.
// QK^T and PV via mma.sync bf16 3-term split. Unstable softmax
// exactly as reference (e=exp(s/8) or 0; den clipped 2e-15).
// smem planes per stage: Kh,Kl,Vh,Vl each 64 rows x 144B pitch.
// ============================================================
#define ARS 144u
#define APL 9216u
#define ASTG 36864u
#define ATT_SMEM (2 * 36864)

__global__ __launch_bounds__(128) void attn_mma(
    const __nv_bfloat16* __restrict__ qh, const __nv_bfloat16* __restrict__ ql,
    const __nv_bfloat16* __restrict__ kh, const __nv_bfloat16* __restrict__ kl,
    const __nv_bfloat16* __restrict__ vh, const __nv_bfloat16* __restrict__ vl,
    const float* __restrict__ qm, const float* __restrict__ km,
    __nv_bfloat16* __restrict__ ch, __nv_bfloat16* __restrict__ cl)
{
    extern __shared__ __align__(128) char asmem[];
    __shared__ float km_s[Ln];
    const uint32_t base = smem_u32(asmem);
    const int tid = threadIdx.x;
    const int lane = tid & 31, wid = tid >> 5;
    const int g = blockIdx.y;
    const int q0 = blockIdx.x << 6;
    const int mb = g & 7;
    const size_t gbase = (size_t)g * (Ln * DH);

    // k_mask row to smem
    for (int i = tid; i < Ln / 4; i += 128)
        ((float4*)km_s)[i] = ((const float4*)(km + mb * Ln))[i];

    // Q tile (hi plane 0, lo plane 1) into stage-0 smem
    #pragma unroll
    for (int i = 0; i < 8; i++) {
        int id = i * 128 + tid;
        int pl = id >> 9, r = (id >> 3) & 63, seg = id & 7;
        const __nv_bfloat16* src = (pl ? ql : qh) + gbase + (size_t)(q0 + r) * DH + seg * 8;
        CP16(base + (uint32_t)pl * APL + (uint32_t)r * ARS + (uint32_t)seg * 16, src);
    }
    CP_COMMIT();
    CP_WAIT0();
    __syncthreads();

    uint32_t qa_h[4][4], qa_l[4][4];
    {
        uint32_t ab = base + (uint32_t)(wid * 16 + (lane & 15)) * ARS
                    + (uint32_t)(lane >> 4) * 16;
        #pragma unroll
        for (int kb = 0; kb < 4; kb++) {
            ldm_x4(qa_h[kb], ab + kb * 32);
            ldm_x4(qa_l[kb], ab + APL + kb * 32);
        }
    }
    __syncthreads();   // Q smem consumed; safe to overwrite with K/V

    const float qm0 = qm[mb * Ln + q0 + wid * 16 + (lane >> 2)];
    const float qm1 = qm[mb * Ln + q0 + wid * 16 + (lane >> 2) + 8];

    float o[8][4] = {};
    float den0 = 0.f, den1 = 0.f;

    // prologue: K/V tile 0 -> stage 0
    #pragma unroll
    for (int i = 0; i < 16; i++) {
        int id = i * 128 + tid;
        int pl = id >> 9, r = (id >> 3) & 63, seg = id & 7;
        const __nv_bfloat16* bp = (pl == 0) ? kh : (pl == 1) ? kl : (pl == 2) ? vh : vl;
        CP16(base + (uint32_t)pl * APL + (uint32_t)r * ARS + (uint32_t)seg * 16,
             bp + gbase + (size_t)r * DH + seg * 8);
    }
    CP_COMMIT();

    for (int t = 0; t < 16; t++) {
        if (t < 15) {
            uint32_t sb2 = base + (uint32_t)((t + 1) & 1) * ASTG;
            int k0n = (t + 1) << 6;
            #pragma unroll
            for (int i = 0; i < 16; i++) {
                int id = i * 128 + tid;
                int pl = id >> 9, r = (id >> 3) & 63, seg = id & 7;
                const __nv_bfloat16* bp = (pl == 0) ? kh : (pl == 1) ? kl : (pl == 2) ? vh : vl;
                CP16(sb2 + (uint32_t)pl * APL + (uint32_t)r * ARS + (uint32_t)seg * 16,
                     bp + gbase + (size_t)(k0n + r) * DH + seg * 8);
            }
            CP_COMMIT();
            CP_WAIT1();
        } else {
            CP_WAIT0();
        }
        __syncthreads();

        const uint32_t sb = base + (uint32_t)(t & 1) * ASTG;

        // ---- S = Q K^T (3-term) ----
        float s[8][4];
        #pragma unroll
        for (int j = 0; j < 8; j++)
            #pragma unroll
            for (int c = 0; c < 4; c++) s[j][c] = 0.f;

        const uint32_t bb = sb + (uint32_t)(lane & 7) * ARS
                          + (uint32_t)((lane >> 3) & 1) * 16;
        #pragma unroll
        for (int j = 0; j < 8; j++) {
            #pragma unroll
            for (int kb = 0; kb < 4; kb++) {
                uint32_t bh2[2], bl2[2];
                ldm_x2(bh2, bb + (uint32_t)j * (8 * ARS) + kb * 32);
                ldm_x2(bl2, bb + APL + (uint32_t)j * (8 * ARS) + kb * 32);
                mma16816(s[j], qa_h[kb], bh2);
                mma16816(s[j], qa_h[kb], bl2);
                mma16816(s[j], qa_l[kb], bh2);
            }
        }

        // ---- mask + exp + den ----
        float e[8][4];
        const int kcb = (t << 6) + ((lane & 3) << 1);
        #pragma unroll
        for (int j = 0; j < 8; j++) {
            float km0v = km_s[(kcb + j * 8) & (Ln - 1)];
            float km1v = km_s[(kcb + j * 8 + 1) & (Ln - 1)];
            e[j][0] = (qm0 * km0v == 0.f) ? 0.f : __expf(s[j][0] * 0.125f);
            e[j][1] = (qm0 * km1v == 0.f) ? 0.f : __expf(s[j][1] * 0.125f);
            e[j][2] = (qm1 * km0v == 0.f) ? 0.f : __expf(s[j][2] * 0.125f);
            e[j][3] = (qm1 * km1v == 0.f) ? 0.f : __expf(s[j][3] * 0.125f);
            den0 += e[j][0] + e[j][1];
            den1 += e[j][2] + e[j][3];
        }

        // ---- O += P V (3-term, P split in regs) ----
        const uint32_t vb = sb + 2 * APL + (uint32_t)(lane & 15) * ARS;
        #pragma unroll
        for (int tt = 0; tt < 4; tt++) {
            uint32_t ah2[4], al2[4];
            split2(e[2 * tt][0],     e[2 * tt][1],     ah2[0], al2[0]);
            split2(e[2 * tt][2],     e[2 * tt][3],     ah2[1], al2[1]);
            split2(e[2 * tt + 1][0], e[2 * tt + 1][1], ah2[2], al2[2]);
            split2(e[2 * tt + 1][2], e[2 * tt + 1][3], ah2[3], al2[3]);
            #pragma unroll
            for (int jd = 0; jd < 8; jd++) {
                uint32_t vh2[2], vl2[2];
                ldm_x2t(vh2, vb + (uint32_t)tt * (16 * ARS) + jd * 16);
                ldm_x2t(vl2, vb + APL + (uint32_t)tt * (16 * ARS) + jd * 16);
                mma16816(o[jd], ah2, vh2);
                mma16816(o[jd], ah2, vl2);
                mma16816(o[jd], al2, vh2);
            }
        }
        __syncthreads();
    }

    // reduce den across the 4 lanes sharing each row
    den0 += __shfl_xor_sync(0xffffffffu, den0, 1);
    den0 += __shfl_xor_sync(0xffffffffu, den0, 2);
    den1 += __shfl_xor_sync(0xffffffffu, den1, 1);
    den1 += __shfl_xor_sync(0xffffffffu, den1, 2);
    const float i0 = 1.f / fmaxf(den0, 2e-15f);
    const float i1 = 1.f / fmaxf(den1, 2e-15f);

    const int row0 = q0 + wid * 16 + (lane >> 2);
    const int colb = (lane & 3) << 1;
    #pragma unroll
    for (int jd = 0; jd < 8; jd++) {
        int col = jd * 8 + colb;
        float v0 = o[jd][0] * i0, v1 = o[jd][1] * i0;
        float v2 = o[jd][2] * i1, v3 = o[jd][3] * i1;
        size_t off0 = gbase + (size_t)row0 * DH + col;
        size_t off1 = off0 + 8 * DH;
        uint32_t h0, l0, h1, l1;
        split2(v0, v1, h0, l0);
        split2(v2, v3, h1, l1);
        ((uint32_t*)ch)[off0 >> 1] = h0;
        ((uint32_t*)cl)[off0 >> 1] = l0;
        ((uint32_t*)ch)[off1 >> 1] = h1;
        ((uint32_t*)cl)[off1 >> 1] = l1;
    }
}

// ============================================================
// LayerNorm
// ============================================================
__global__ __launch_bounds__(256) void ln_kernel(
    const float* __restrict__ y, const float* __restrict__ gamma,
    const float* __restrict__ beta, float* __restrict__ out)
{
    __shared__ float red[8];
    int row = blockIdx.x, tid = threadIdx.x;
    float4 v = ((const float4*)(y + (size_t)row * Dn))[tid];

    float s = v.x + v.y + v.z + v.w;
    #pragma unroll
    for (int o = 16; o; o >>= 1) s += __shfl_xor_sync(0xffffffffu, s, o);
    if ((tid & 31) == 0) red[tid >> 5] = s;
    __syncthreads();
    if (tid < 32) {
        float t = (tid < 8) ? red[tid] : 0.f;
        #pragma unroll
        for (int o = 4; o; o >>= 1) t += __shfl_xor_sync(0xffffffffu, t, o);
        if (tid == 0) red[0] = t;
    }
    __syncthreads();
    float mean = red[0] * (1.f / Dn);
    __syncthreads();

    float dx = v.x - mean, dy = v.y - mean, dz = v.z - mean, dw = v.w - mean;
    float sq = dx * dx + dy * dy + dz * dz + dw * dw;
    #pragma unroll
    for (int o = 16; o; o >>= 1) sq += __shfl_xor_sync(0xffffffffu, sq, o);
    if ((tid & 31) == 0) red[tid >> 5] = sq;
    __syncthreads();
    if (tid < 32) {
        float t = (tid < 8) ? red[tid] : 0.f;
        #pragma unroll
        for (int o = 4; o; o >>= 1) t += __shfl_xor_sync(0xffffffffu, t, o);
        if (tid == 0) red[0] = t;
    }
    __syncthreads();
    float rstd = rsqrtf(red[0] * (1.f / Dn) + 1e-5f);

    float4 g4 = ((const float4*)gamma)[tid];
    float4 b4 = ((const float4*)beta)[tid];
    float4 o4;
    o4.x = dx * rstd * g4.x + b4.x;
    o4.y = dy * rstd * g4.y + b4.y;
    o4.z = dz * rstd * g4.z + b4.z;
    o4.w = dw * rstd * g4.w + b4.w;
    ((float4*)(out + (size_t)row * Dn))[tid] = o4;
}

// ============================================================
extern "C" void kernel_launch(void* const* d_in, const int* in_sizes, int n_in,
                              void* d_out, int out_size)
{
    const float* query  = (const float*)d_in[0];
    const float* key_   = (const float*)d_in[1];
    const float* value  = (const float*)d_in[2];
    const float* q_mask = (const float*)d_in[3];
    const float* k_mask = (const float*)d_in[4];
    const float* Wq = (const float*)d_in[5];
    const float* bq = (const float*)d_in[6];
    const float* Wk = (const float*)d_in[7];
    const float* bk = (const float*)d_in[8];
    const float* Wv = (const float*)d_in[9];
    const float* bv = (const float*)d_in[10];
    const float* Wo = (const float*)d_in[11];
    const float* bo = (const float*)d_in[12];
    const float* gamma = (const float*)d_in[13];
    const float* beta  = (const float*)d_in[14];

    float* y;
    cudaGetSymbolAddress((void**)&y, g_y);

    __nv_bfloat16 *sh, *sl, *qh, *ql, *kh, *kl, *vh, *vl, *ch, *cl;
    __nv_bfloat16 *wqh, *wql, *wkh, *wkl, *wvh, *wvl, *woh, *wol;
    cudaGetSymbolAddress((void**)&sh, g_sh);  cudaGetSymbolAddress((void**)&sl, g_sl);
    cudaGetSymbolAddress((void**)&qh, g_qh);  cudaGetSymbolAddress((void**)&ql, g_ql);
    cudaGetSymbolAddress((void**)&kh, g_kh);  cudaGetSymbolAddress((void**)&kl, g_kl);
    cudaGetSymbolAddress((void**)&vh, g_vh);  cudaGetSymbolAddress((void**)&vl, g_vl);
    cudaGetSymbolAddress((void**)&ch, g_ch);  cudaGetSymbolAddress((void**)&cl, g_cl);
    cudaGetSymbolAddress((void**)&wqh, g_wqh); cudaGetSymbolAddress((void**)&wql, g_wql);
    cudaGetSymbolAddress((void**)&wkh, g_wkh); cudaGetSymbolAddress((void**)&wkl, g_wkl);
    cudaGetSymbolAddress((void**)&wvh, g_wvh); cudaGetSymbolAddress((void**)&wvl, g_wvl);
    cudaGetSymbolAddress((void**)&woh, g_woh); cudaGetSymbolAddress((void**)&wol, g_wol);

    cudaFuncSetAttribute(gemm_mma, cudaFuncAttributeMaxDynamicSharedMemorySize, GM_SMEM);
    cudaFuncSetAttribute(attn_mma, cudaFuncAttributeMaxDynamicSharedMemorySize, ATT_SMEM);

    const int n4_act = (Mn * Dn) / 4;
    const int n4_w   = (Dn * Dn) / 4;

    // weight splits
    split_kernel<<<n4_w / 256, 256>>>(Wq, wqh, wql, n4_w);
    split_kernel<<<n4_w / 256, 256>>>(Wk, wkh, wkl, n4_w);
    split_kernel<<<n4_w / 256, 256>>>(Wv, wvh, wvl, n4_w);
    split_kernel<<<n4_w / 256, 256>>>(Wo, woh, wol, n4_w);

    dim3 gg(Dn / 128, Mn / 128);

    // Q projection
    split_kernel<<<n4_act / 256, 256>>>(query, sh, sl, n4_act);
    gemm_mma<<<gg, 256, GM_SMEM>>>(sh, sl, wqh, wql, bq, nullptr, nullptr, qh, ql);
    // K projection
    split_kernel<<<n4_act / 256, 256>>>(key_, sh, sl, n4_act);
    gemm_mma<<<gg, 256, GM_SMEM>>>(sh, sl, wkh, wkl, bk, nullptr, nullptr, kh, kl);
    // V projection
    split_kernel<<<n4_act / 256, 256>>>(value, sh, sl, n4_act);
    gemm_mma<<<gg, 256, GM_SMEM>>>(sh, sl, wvh, wvl, bv, nullptr, nullptr, vh, vl);

    // attention (tensor core)
    attn_mma<<<dim3(Ln / 64, Bn * Hn), 128, ATT_SMEM>>>(
        qh, ql, kh, kl, vh, vl, q_mask, k_mask, ch, cl);

    // output projection + residual
    gemm_mma<<<gg, 256, GM_SMEM>>>(ch, cl, woh, wol, bo, query, y, nullptr, nullptr);

    ln_kernel<<<Mn, 256>>>(y, gamma, beta, (float*)d_out);
}